// round 2
// baseline (speedup 1.0000x reference)
#include <cuda_runtime.h>
#include <cuda_bf16.h>
#include <math.h>

// ---------------- problem constants ----------------
#define BATCH 2
#define TLEN  1024
#define DMODEL 1024
#define NHEAD 16
#define HDIM 64
#define NLAYER 6
#define VOCAB 32000
#define DFF 4096
#define NROWS (BATCH*TLEN)   // 2048

// ---------------- scratch (device globals; no allocations allowed) ----------
__device__ float g_x[NROWS*DMODEL];
__device__ float g_h[NROWS*DMODEL];
__device__ float g_q[NROWS*DMODEL];
__device__ float g_k[NROWS*DMODEL];
__device__ float g_v[NROWS*DMODEL];
__device__ float g_attn[NROWS*DMODEL];
__device__ float g_ff[NROWS*DFF];

// ---------------- embed ----------------
__global__ __launch_bounds__(256) void embed_kernel(
    const int* __restrict__ idx, const float* __restrict__ tok,
    const float* __restrict__ pos, float* __restrict__ x)
{
    int i = blockIdx.x * blockDim.x + threadIdx.x;   // float4 index
    int row = i >> 8;            // 0..2047
    int c4  = (i & 255) * 4;     // column
    int t = row & (TLEN - 1);
    int token = idx[row];
    float4 a = *(const float4*)(tok + (size_t)token * DMODEL + c4);
    float4 p = *(const float4*)(pos + (size_t)t * DMODEL + c4);
    float4 o; o.x = a.x + p.x; o.y = a.y + p.y; o.z = a.z + p.z; o.w = a.w + p.w;
    *(float4*)(x + (size_t)row * DMODEL + c4) = o;
}

// ---------------- layernorm ----------------
__device__ __forceinline__ float block_sum256(float v, float* sbuf)
{
    #pragma unroll
    for (int o = 16; o; o >>= 1) v += __shfl_xor_sync(0xffffffffu, v, o);
    int w = threadIdx.x >> 5;
    if ((threadIdx.x & 31) == 0) sbuf[w] = v;
    __syncthreads();
    if (threadIdx.x < 32) {
        float r = (threadIdx.x < 8) ? sbuf[threadIdx.x] : 0.f;
        #pragma unroll
        for (int o = 4; o; o >>= 1) r += __shfl_xor_sync(0xffffffffu, r, o);
        if (threadIdx.x == 0) sbuf[0] = r;
    }
    __syncthreads();
    float out = sbuf[0];
    __syncthreads();   // sbuf reused by caller
    return out;
}

__global__ __launch_bounds__(256) void ln_kernel(
    const float* __restrict__ x, const float* __restrict__ g,
    const float* __restrict__ b, float* __restrict__ out)
{
    __shared__ float sbuf[8];
    size_t row = blockIdx.x;
    const float* xr = x + row * DMODEL;
    int c = threadIdx.x * 4;
    float4 d = *(const float4*)(xr + c);
    float mean = block_sum256(d.x + d.y + d.z + d.w, sbuf) * (1.f / DMODEL);
    float ex = d.x - mean, ey = d.y - mean, ez = d.z - mean, ew = d.w - mean;
    float var = block_sum256(ex*ex + ey*ey + ez*ez + ew*ew, sbuf) * (1.f / DMODEL);
    float inv = rsqrtf(var + 1e-5f);
    float4 gg = *(const float4*)(g + c);
    float4 bb = *(const float4*)(b + c);
    float4 o;
    o.x = ex * inv * gg.x + bb.x;
    o.y = ey * inv * gg.y + bb.y;
    o.z = ez * inv * gg.z + bb.z;
    o.w = ew * inv * gg.w + bb.w;
    *(float4*)(out + row * DMODEL + c) = o;
}

// ---------------- generic GEMM: C = A(MxK) * B(KxN) [+bias][+res][relu] ----
// HEADB: B is per-head blocked: element(k, n) at B + (n>>6)*head_stride + k*64 + (n&63)
#define BM 128
#define BN 128
#define BK 16
#define PAD 4

template<bool HEADB, bool BIAS, bool RELU, bool RES>
__global__ __launch_bounds__(256) void gemm_kernel(
    const float* __restrict__ A, const float* __restrict__ B,
    const float* __restrict__ bias, const float* __restrict__ res,
    float* __restrict__ C, int M, int N, int K, int head_stride)
{
    __shared__ float As[BK][BM + PAD];
    __shared__ float Bs[BK][BN + PAD];
    int tid = threadIdx.x;
    int n0 = blockIdx.x * BN, m0 = blockIdx.y * BM;
    int tx = tid & 15, ty = tid >> 4;

    float acc[8][8];
    #pragma unroll
    for (int i = 0; i < 8; i++)
        #pragma unroll
        for (int j = 0; j < 8; j++) acc[i][j] = 0.f;

    int arow = tid >> 2;       // 0..63
    int aq   = tid & 3;        // k-quad

    for (int k0 = 0; k0 < K; k0 += BK) {
        #pragma unroll
        for (int it = 0; it < 2; it++) {
            int row = arow + it * 64;
            float4 vv = *(const float4*)(A + (size_t)(m0 + row) * K + k0 + aq * 4);
            As[aq*4+0][row] = vv.x;
            As[aq*4+1][row] = vv.y;
            As[aq*4+2][row] = vv.z;
            As[aq*4+3][row] = vv.w;
        }
        #pragma unroll
        for (int it = 0; it < 2; it++) {
            int idx = tid + it * 256;
            int r = idx >> 5;        // 0..15
            int q = idx & 31;        // 0..31
            const float* src;
            if (HEADB) {
                int cg = n0 + q * 4;
                src = B + (size_t)(cg >> 6) * head_stride + (size_t)(k0 + r) * 64 + (cg & 63);
            } else {
                src = B + (size_t)(k0 + r) * N + n0 + q * 4;
            }
            *(float4*)(&Bs[r][q * 4]) = *(const float4*)src;
        }
        __syncthreads();
        #pragma unroll
        for (int kk = 0; kk < BK; kk++) {
            float a[8], b[8];
            *(float4*)(a)     = *(float4*)(&As[kk][ty * 8]);
            *(float4*)(a + 4) = *(float4*)(&As[kk][ty * 8 + 4]);
            *(float4*)(b)     = *(float4*)(&Bs[kk][tx * 8]);
            *(float4*)(b + 4) = *(float4*)(&Bs[kk][tx * 8 + 4]);
            #pragma unroll
            for (int i = 0; i < 8; i++)
                #pragma unroll
                for (int j = 0; j < 8; j++)
                    acc[i][j] += a[i] * b[j];
        }
        __syncthreads();
    }

    #pragma unroll
    for (int i = 0; i < 8; i++) {
        size_t m = m0 + ty * 8 + i;
        #pragma unroll
        for (int j = 0; j < 8; j++) {
            size_t n = n0 + tx * 8 + j;
            float vv = acc[i][j];
            if (BIAS) vv += bias[n];
            if (RES)  vv += res[m * N + n];
            if (RELU) vv = fmaxf(vv, 0.f);
            C[m * N + n] = vv;
        }
    }
}

// ---------------- flash attention (fp32) ----------------
// q,k,v,o layout: [b*T + t][h*64 + e] (row-major 2048x1024)
// one block: 64 query rows for one (b,h); loop over key tiles <= query tile
#define ASTR 65

extern __shared__ float attn_smem[];

__global__ __launch_bounds__(256) void attn_kernel(
    const float* __restrict__ q, const float* __restrict__ k,
    const float* __restrict__ v, float* __restrict__ o)
{
    int qt = blockIdx.x;      // 0..15
    int h  = blockIdx.y;      // 0..15
    int b  = blockIdx.z;      // 0..1

    float* qs = attn_smem;
    float* ks = qs + 64 * ASTR;
    float* vs = ks + 64 * ASTR;
    float* ps = vs + 64 * ASTR;

    int tid = threadIdx.x, tx = tid & 15, ty = tid >> 4;
    size_t baseRow = (size_t)b * TLEN;
    int cofs = h * HDIM;

    // load Q tile
    #pragma unroll
    for (int it = 0; it < 4; it++) {
        int idx = it * 256 + tid;
        int r = idx >> 4, c4 = (idx & 15) * 4;
        float4 d = *(const float4*)(q + (baseRow + qt * 64 + r) * DMODEL + cofs + c4);
        qs[r * ASTR + c4 + 0] = d.x; qs[r * ASTR + c4 + 1] = d.y;
        qs[r * ASTR + c4 + 2] = d.z; qs[r * ASTR + c4 + 3] = d.w;
    }

    float m_i[4], l_i[4], oacc[4][4];
    #pragma unroll
    for (int i = 0; i < 4; i++) {
        m_i[i] = -1e30f; l_i[i] = 0.f;
        #pragma unroll
        for (int j = 0; j < 4; j++) oacc[i][j] = 0.f;
    }

    for (int jt = 0; jt <= qt; jt++) {
        __syncthreads();   // done reading ks/vs/ps from prev iter; qs visible 1st iter
        #pragma unroll
        for (int it = 0; it < 4; it++) {
            int idx = it * 256 + tid;
            int r = idx >> 4, c4 = (idx & 15) * 4;
            float4 dk = *(const float4*)(k + (baseRow + jt * 64 + r) * DMODEL + cofs + c4);
            ks[r * ASTR + c4 + 0] = dk.x; ks[r * ASTR + c4 + 1] = dk.y;
            ks[r * ASTR + c4 + 2] = dk.z; ks[r * ASTR + c4 + 3] = dk.w;
            float4 dv = *(const float4*)(v + (baseRow + jt * 64 + r) * DMODEL + cofs + c4);
            vs[r * ASTR + c4 + 0] = dv.x; vs[r * ASTR + c4 + 1] = dv.y;
            vs[r * ASTR + c4 + 2] = dv.z; vs[r * ASTR + c4 + 3] = dv.w;
        }
        __syncthreads();

        // S = Q K^T * scale
        float s[4][4];
        #pragma unroll
        for (int i = 0; i < 4; i++)
            #pragma unroll
            for (int j = 0; j < 4; j++) s[i][j] = 0.f;
        for (int d = 0; d < 64; d++) {
            float a[4], bb[4];
            #pragma unroll
            for (int i = 0; i < 4; i++) a[i] = qs[(ty * 4 + i) * ASTR + d];
            #pragma unroll
            for (int j = 0; j < 4; j++) bb[j] = ks[(tx * 4 + j) * ASTR + d];
            #pragma unroll
            for (int i = 0; i < 4; i++)
                #pragma unroll
                for (int j = 0; j < 4; j++) s[i][j] += a[i] * bb[j];
        }
        const float scale = 0.125f;   // HD^-0.5
        #pragma unroll
        for (int i = 0; i < 4; i++)
            #pragma unroll
            for (int j = 0; j < 4; j++) {
                s[i][j] *= scale;
                if (jt == qt && (tx * 4 + j) > (ty * 4 + i)) s[i][j] = -1e30f;
            }

        // online softmax
        #pragma unroll
        for (int i = 0; i < 4; i++) {
            float rmax = fmaxf(fmaxf(s[i][0], s[i][1]), fmaxf(s[i][2], s[i][3]));
            #pragma unroll
            for (int off = 8; off; off >>= 1)
                rmax = fmaxf(rmax, __shfl_xor_sync(0xffffffffu, rmax, off, 16));
            float mnew = fmaxf(m_i[i], rmax);
            float alpha = __expf(m_i[i] - mnew);
            float rsum = 0.f;
            #pragma unroll
            for (int j = 0; j < 4; j++) {
                s[i][j] = __expf(s[i][j] - mnew);
                rsum += s[i][j];
            }
            #pragma unroll
            for (int off = 8; off; off >>= 1)
                rsum += __shfl_xor_sync(0xffffffffu, rsum, off, 16);
            l_i[i] = l_i[i] * alpha + rsum;
            m_i[i] = mnew;
            #pragma unroll
            for (int j = 0; j < 4; j++) oacc[i][j] *= alpha;
            #pragma unroll
            for (int j = 0; j < 4; j++)
                ps[(ty * 4 + i) * ASTR + tx * 4 + j] = s[i][j];
        }
        __syncthreads();

        // O += P V
        for (int kc = 0; kc < 64; kc++) {
            float a[4], bb[4];
            #pragma unroll
            for (int i = 0; i < 4; i++) a[i] = ps[(ty * 4 + i) * ASTR + kc];
            #pragma unroll
            for (int j = 0; j < 4; j++) bb[j] = vs[kc * ASTR + tx * 4 + j];
            #pragma unroll
            for (int i = 0; i < 4; i++)
                #pragma unroll
                for (int j = 0; j < 4; j++) oacc[i][j] += a[i] * bb[j];
        }
    }

    // write normalized output
    #pragma unroll
    for (int i = 0; i < 4; i++) {
        float invl = 1.f / l_i[i];
        size_t row = baseRow + qt * 64 + ty * 4 + i;
        #pragma unroll
        for (int j = 0; j < 4; j++)
            o[row * DMODEL + cofs + tx * 4 + j] = oacc[i][j] * invl;
    }
}

// ---------------- launcher ----------------
extern "C" void kernel_launch(void* const* d_in, const int* in_sizes, int n_in,
                              void* d_out, int out_size)
{
    const int*   idx  = (const int*)d_in[0];
    const float* tok  = (const float*)d_in[1];
    const float* pos  = (const float*)d_in[2];
    const float* Wq   = (const float*)d_in[3];
    const float* Wk   = (const float*)d_in[4];
    const float* Wv   = (const float*)d_in[5];
    const float* Wo   = (const float*)d_in[6];
    const float* bo   = (const float*)d_in[7];
    const float* ln1g = (const float*)d_in[8];
    const float* ln1b = (const float*)d_in[9];
    const float* ln2g = (const float*)d_in[10];
    const float* ln2b = (const float*)d_in[11];
    const float* W1   = (const float*)d_in[12];
    const float* b1   = (const float*)d_in[13];
    const float* W2   = (const float*)d_in[14];
    const float* b2   = (const float*)d_in[15];
    const float* lnfg = (const float*)d_in[16];
    const float* lnfb = (const float*)d_in[17];
    const float* Wh   = (const float*)d_in[18];
    const float* bh   = (const float*)d_in[19];
    float* out = (float*)d_out;

    float *x, *h, *q, *k, *v, *attn, *ff;
    cudaGetSymbolAddress((void**)&x, g_x);
    cudaGetSymbolAddress((void**)&h, g_h);
    cudaGetSymbolAddress((void**)&q, g_q);
    cudaGetSymbolAddress((void**)&k, g_k);
    cudaGetSymbolAddress((void**)&v, g_v);
    cudaGetSymbolAddress((void**)&attn, g_attn);
    cudaGetSymbolAddress((void**)&ff, g_ff);

    const int attn_smem_bytes = 4 * 64 * ASTR * sizeof(float);  // ~66.5 KB
    cudaFuncSetAttribute(attn_kernel, cudaFuncAttributeMaxDynamicSharedMemorySize,
                         attn_smem_bytes);

    // embed
    embed_kernel<<<NROWS, 256>>>(idx, tok, pos, x);

    const size_t wqkv_l = (size_t)NHEAD * DMODEL * HDIM;  // 1048576
    const size_t wo_l   = (size_t)DMODEL * DMODEL;
    const size_t w1_l   = (size_t)DMODEL * DFF;
    const size_t w2_l   = (size_t)DFF * DMODEL;

    dim3 gD(DMODEL / BN, NROWS / BM);    // 8 x 16
    dim3 gF(DFF / BN, NROWS / BM);       // 32 x 16
    dim3 gV(VOCAB / BN, NROWS / BM);     // 250 x 16

    for (int l = 0; l < NLAYER; l++) {
        // ln1
        ln_kernel<<<NROWS, 256>>>(x, ln1g + l * DMODEL, ln1b + l * DMODEL, h);
        // qkv (per-head blocked weights)
        gemm_kernel<true, false, false, false><<<gD, 256>>>(
            h, Wq + l * wqkv_l, nullptr, nullptr, q, NROWS, DMODEL, DMODEL, DMODEL * HDIM);
        gemm_kernel<true, false, false, false><<<gD, 256>>>(
            h, Wk + l * wqkv_l, nullptr, nullptr, k, NROWS, DMODEL, DMODEL, DMODEL * HDIM);
        gemm_kernel<true, false, false, false><<<gD, 256>>>(
            h, Wv + l * wqkv_l, nullptr, nullptr, v, NROWS, DMODEL, DMODEL, DMODEL * HDIM);
        // attention
        attn_kernel<<<dim3(TLEN / 64, NHEAD, BATCH), 256, attn_smem_bytes>>>(q, k, v, attn);
        // out proj + residual
        gemm_kernel<false, true, false, true><<<gD, 256>>>(
            attn, Wo + l * wo_l, bo + l * DMODEL, x, x, NROWS, DMODEL, DMODEL, 0);
        // ln2
        ln_kernel<<<NROWS, 256>>>(x, ln2g + l * DMODEL, ln2b + l * DMODEL, h);
        // ffn1 (+bias, relu)
        gemm_kernel<false, true, true, false><<<gF, 256>>>(
            h, W1 + l * w1_l, b1 + (size_t)l * DFF, nullptr, ff, NROWS, DFF, DMODEL, 0);
        // ffn2 (+bias, residual)
        gemm_kernel<false, true, false, true><<<gD, 256>>>(
            ff, W2 + l * w2_l, b2 + l * DMODEL, x, x, NROWS, DMODEL, DFF, 0);
    }

    // final LN + head
    ln_kernel<<<NROWS, 256>>>(x, lnfg, lnfb, h);
    gemm_kernel<false, true, false, false><<<gV, 256>>>(
        h, Wh, bh, nullptr, out, NROWS, VOCAB, DMODEL, 0);
}

// round 4
// speedup vs baseline: 2.6111x; 2.6111x over previous
#include <cuda_runtime.h>
#include <cuda_bf16.h>
#include <math.h>
#include <stdint.h>

// ---------------- problem constants ----------------
#define BATCH 2
#define TLEN  1024
#define DMODEL 1024
#define NHEAD 16
#define HDIM 64
#define NLAYER 6
#define VOCAB 32000
#define DFF 4096
#define NROWS (BATCH*TLEN)   // 2048

// ---------------- scratch (device globals; no allocations allowed) ----------
__device__ float g_x[NROWS*DMODEL];
__device__ float g_h[NROWS*DMODEL];
__device__ float g_q[NROWS*DMODEL];
__device__ float g_k[NROWS*DMODEL];
__device__ float g_v[NROWS*DMODEL];
__device__ float g_attn[NROWS*DMODEL];
__device__ float g_ff[NROWS*DFF];

// converted activations (bf16 hi/lo), max 2048x4096
__device__ __nv_bfloat16 g_act_hi[NROWS*DFF];
__device__ __nv_bfloat16 g_act_lo[NROWS*DFF];

// converted transposed weights arena
#define WARENA_ELEMS (2ull*(6ull*(4ull*1048576ull + 2ull*4194304ull) + 32768000ull))
__device__ __nv_bfloat16 g_wbuf[WARENA_ELEMS];

// shared dynamic smem symbol
extern __shared__ __align__(1024) char g_smem[];

// ================= PTX helpers (sm_80-level only; no arch-'a' features) =====
__device__ __forceinline__ uint32_t smem_u32(const void* p) {
    uint32_t a;
    asm("{ .reg .u64 t; cvta.to.shared.u64 t, %1; cvt.u32.u64 %0, t; }" : "=r"(a) : "l"(p));
    return a;
}
__device__ __forceinline__ void cp_async16(uint32_t sm, const void* g) {
    asm volatile("cp.async.cg.shared.global [%0], [%1], 16;" :: "r"(sm), "l"(g) : "memory");
}
#define CP_COMMIT() asm volatile("cp.async.commit_group;" ::: "memory")
#define CP_WAIT2()  asm volatile("cp.async.wait_group 2;" ::: "memory")

__device__ __forceinline__ void ldsm4(uint32_t* r, uint32_t addr) {
    asm volatile("ldmatrix.sync.aligned.m8n8.x4.shared.b16 {%0,%1,%2,%3}, [%4];"
        : "=r"(r[0]), "=r"(r[1]), "=r"(r[2]), "=r"(r[3]) : "r"(addr));
}
__device__ __forceinline__ void mma_bf16(float* c, const uint32_t* a, const uint32_t* b) {
    asm volatile(
        "mma.sync.aligned.m16n8k16.row.col.f32.bf16.bf16.f32 "
        "{%0,%1,%2,%3}, {%4,%5,%6,%7}, {%8,%9}, {%0,%1,%2,%3};"
        : "+f"(c[0]), "+f"(c[1]), "+f"(c[2]), "+f"(c[3])
        : "r"(a[0]), "r"(a[1]), "r"(a[2]), "r"(a[3]), "r"(b[0]), "r"(b[1]));
}

#define SW128(off) ((off) ^ (((off) >> 3) & 0x70))

// ---------------- embed ----------------
__global__ __launch_bounds__(256) void embed_kernel(
    const int* __restrict__ idx, const float* __restrict__ tok,
    const float* __restrict__ pos, float* __restrict__ x)
{
    int i = blockIdx.x * blockDim.x + threadIdx.x;
    int row = i >> 8;
    int c4  = (i & 255) * 4;
    int t = row & (TLEN - 1);
    int token = idx[row];
    float4 a = *(const float4*)(tok + (size_t)token * DMODEL + c4);
    float4 p = *(const float4*)(pos + (size_t)t * DMODEL + c4);
    float4 o; o.x = a.x + p.x; o.y = a.y + p.y; o.z = a.z + p.z; o.w = a.w + p.w;
    *(float4*)(x + (size_t)row * DMODEL + c4) = o;
}

// ---------------- layernorm ----------------
__device__ __forceinline__ float block_sum256(float v, float* sbuf)
{
    #pragma unroll
    for (int o = 16; o; o >>= 1) v += __shfl_xor_sync(0xffffffffu, v, o);
    int w = threadIdx.x >> 5;
    if ((threadIdx.x & 31) == 0) sbuf[w] = v;
    __syncthreads();
    if (threadIdx.x < 32) {
        float r = (threadIdx.x < 8) ? sbuf[threadIdx.x] : 0.f;
        #pragma unroll
        for (int o = 4; o; o >>= 1) r += __shfl_xor_sync(0xffffffffu, r, o);
        if (threadIdx.x == 0) sbuf[0] = r;
    }
    __syncthreads();
    float out = sbuf[0];
    __syncthreads();
    return out;
}

__global__ __launch_bounds__(256) void ln_kernel(
    const float* __restrict__ x, const float* __restrict__ g,
    const float* __restrict__ b, float* __restrict__ out)
{
    __shared__ float sbuf[8];
    size_t row = blockIdx.x;
    const float* xr = x + row * DMODEL;
    int c = threadIdx.x * 4;
    float4 d = *(const float4*)(xr + c);
    float mean = block_sum256(d.x + d.y + d.z + d.w, sbuf) * (1.f / DMODEL);
    float ex = d.x - mean, ey = d.y - mean, ez = d.z - mean, ew = d.w - mean;
    float var = block_sum256(ex*ex + ey*ey + ez*ez + ew*ew, sbuf) * (1.f / DMODEL);
    float inv = rsqrtf(var + 1e-5f);
    float4 gg = *(const float4*)(g + c);
    float4 bb = *(const float4*)(b + c);
    float4 o;
    o.x = ex * inv * gg.x + bb.x;
    o.y = ey * inv * gg.y + bb.y;
    o.z = ez * inv * gg.z + bb.z;
    o.w = ew * inv * gg.w + bb.w;
    *(float4*)(out + row * DMODEL + c) = o;
}

// ---------------- fp32 -> bf16 hi/lo split ----------------
__device__ __forceinline__ void split_bf16(float x, __nv_bfloat16& h, __nv_bfloat16& l)
{
    h = __float2bfloat16(x);
    l = __float2bfloat16(x - __bfloat162float(h));
}

__global__ __launch_bounds__(256) void convact_kernel(
    const float* __restrict__ x, __nv_bfloat16* __restrict__ hi,
    __nv_bfloat16* __restrict__ lo)
{
    int i = blockIdx.x * blockDim.x + threadIdx.x;
    float4 v = ((const float4*)x)[i];
    uint2 uh, ul;
    __nv_bfloat16* hp = (__nv_bfloat16*)&uh;
    __nv_bfloat16* lp = (__nv_bfloat16*)&ul;
    split_bf16(v.x, hp[0], lp[0]);
    split_bf16(v.y, hp[1], lp[1]);
    split_bf16(v.z, hp[2], lp[2]);
    split_bf16(v.w, hp[3], lp[3]);
    *(uint2*)(hi + (size_t)i * 4) = uh;
    *(uint2*)(lo + (size_t)i * 4) = ul;
}

// weight transpose + split: input W[K,N] (or per-head gather), output [N,K] hi/lo
template<bool HEADB>
__global__ __launch_bounds__(256) void convw_kernel(
    const float* __restrict__ W, __nv_bfloat16* __restrict__ hi,
    __nv_bfloat16* __restrict__ lo, int K, int N)
{
    __shared__ float sm[32][33];
    int tx = threadIdx.x, ty = threadIdx.y;
    int n0 = blockIdx.x * 32, k0 = blockIdx.y * 32;
    #pragma unroll
    for (int i = 0; i < 4; i++) {
        int k = k0 + ty + i * 8, n = n0 + tx;
        size_t addr = HEADB ? ((size_t)(n >> 6) * (DMODEL * HDIM) + (size_t)k * HDIM + (n & 63))
                            : ((size_t)k * N + n);
        sm[ty + i * 8][tx] = W[addr];
    }
    __syncthreads();
    #pragma unroll
    for (int i = 0; i < 4; i++) {
        int n = n0 + ty + i * 8, k = k0 + tx;
        float v = sm[tx][ty + i * 8];
        __nv_bfloat16 h, l;
        split_bf16(v, h, l);
        hi[(size_t)n * K + k] = h;
        lo[(size_t)n * K + k] = l;
    }
}

// ---------------- mma.sync GEMM: C[M,N] = A[M,K] * Bt[N,K]^T (bf16x3) -------
// BM=BN=128, KC=64, 256 threads (8 warps 2x4, warp tile 64x32), 3-stage cp.async
#define BM 128
#define BN 128
#define KC 64
#define NSTAGE 3
#define TILE_B 16384            // 128 rows x 128 bytes
#define STAGE_B (4*TILE_B)      // Ahi, Alo, Bhi, Blo = 64 KB
#define GEMM_SMEM (NSTAGE*STAGE_B)   // 196608

__device__ __forceinline__ void issue_stage(
    const __nv_bfloat16* __restrict__ a_hi, const __nv_bfloat16* __restrict__ a_lo,
    const __nv_bfloat16* __restrict__ b_hi, const __nv_bfloat16* __restrict__ b_lo,
    int K, int k0, uint32_t st_addr, int tid)
{
    const __nv_bfloat16* srcs[4] = { a_hi + k0, a_lo + k0, b_hi + k0, b_lo + k0 };
    #pragma unroll
    for (int t = 0; t < 4; t++) {
        const __nv_bfloat16* g = srcs[t];
        uint32_t sm = st_addr + t * TILE_B;
        #pragma unroll
        for (int i = 0; i < 4; i++) {
            int idx = i * 256 + tid;
            int r = idx >> 3, u = idx & 7;
            const void* gp = (const char*)(g + (size_t)r * K) + u * 16;
            uint32_t off = (uint32_t)(r * 128 + u * 16);
            cp_async16(sm + SW128(off), gp);
        }
    }
}

template<bool BIAS, bool RELU, bool RES>
__global__ __launch_bounds__(256) void gemm_tc_kernel(
    const __nv_bfloat16* __restrict__ Ahi, const __nv_bfloat16* __restrict__ Alo,
    const __nv_bfloat16* __restrict__ Bhi, const __nv_bfloat16* __restrict__ Blo,
    const float* __restrict__ bias, const float* __restrict__ res,
    float* __restrict__ C, int N, int K)
{
    uint32_t sbase = smem_u32(g_smem);
    int tid = threadIdx.x, lane = tid & 31, wid = tid >> 5;
    int n0 = blockIdx.x * BN, m0 = blockIdx.y * BM;
    int wm = (wid & 1) * 64, wn = (wid >> 1) * 32;
    int NC = K / KC;

    const __nv_bfloat16* a_hi = Ahi + (size_t)m0 * K;
    const __nv_bfloat16* a_lo = Alo + (size_t)m0 * K;
    const __nv_bfloat16* b_hi = Bhi + (size_t)n0 * K;
    const __nv_bfloat16* b_lo = Blo + (size_t)n0 * K;

    float acc[4][4][4];
    #pragma unroll
    for (int i = 0; i < 4; i++)
        #pragma unroll
        for (int j = 0; j < 4; j++)
            #pragma unroll
            for (int r = 0; r < 4; r++) acc[i][j][r] = 0.f;

    // prologue: stages 0..2 <- chunks 0..2   (NC >= 3 always here: K >= 1024)
    #pragma unroll
    for (int s = 0; s < NSTAGE; s++) {
        issue_stage(a_hi, a_lo, b_hi, b_lo, K, s * KC, sbase + s * STAGE_B, tid);
        CP_COMMIT();
    }

    // per-thread fragment addressing constants
    int aq = lane >> 4;                      // A k-half
    int arow_l = lane & 15;
    uint32_t a_sw = (uint32_t)((arow_l & 7) << 4);
    int bq = lane >> 3;                      // B quarter
    int brow_l = lane & 7;
    uint32_t b_sw = (uint32_t)(brow_l << 4);
    uint32_t a_colb0 = (uint32_t)(aq * 16);
    uint32_t b_colb0 = (uint32_t)((bq & 1) * 16);
    int b_rowloc = (bq >> 1) * 8 + brow_l;

    for (int c = 0; c < NC; c++) {
        CP_WAIT2();
        __syncthreads();
        uint32_t st = sbase + (uint32_t)(c % NSTAGE) * STAGE_B;
        uint32_t stA_hi = st, stA_lo = st + TILE_B;
        uint32_t stB_hi = st + 2 * TILE_B, stB_lo = st + 3 * TILE_B;

        #pragma unroll
        for (int ks = 0; ks < 4; ks++) {
            uint32_t a_colb = (uint32_t)(ks * 32) + a_colb0;
            uint32_t b_colb = (uint32_t)(ks * 32) + b_colb0;
            uint32_t ahi_f[4][4], alo_f[4][4], bhi_f[4][2], blo_f[4][2];
            #pragma unroll
            for (int mt = 0; mt < 4; mt++) {
                uint32_t ro = (uint32_t)((wm + mt * 16 + arow_l) * 128);
                ldsm4(ahi_f[mt], stA_hi + ro + (a_colb ^ a_sw));
                ldsm4(alo_f[mt], stA_lo + ro + (a_colb ^ a_sw));
            }
            #pragma unroll
            for (int np = 0; np < 2; np++) {
                uint32_t ro = (uint32_t)((wn + np * 16 + b_rowloc) * 128);
                uint32_t r4[4];
                ldsm4(r4, stB_hi + ro + (b_colb ^ b_sw));
                bhi_f[np*2][0] = r4[0]; bhi_f[np*2][1] = r4[1];
                bhi_f[np*2+1][0] = r4[2]; bhi_f[np*2+1][1] = r4[3];
                ldsm4(r4, stB_lo + ro + (b_colb ^ b_sw));
                blo_f[np*2][0] = r4[0]; blo_f[np*2][1] = r4[1];
                blo_f[np*2+1][0] = r4[2]; blo_f[np*2+1][1] = r4[3];
            }
            #pragma unroll
            for (int mt = 0; mt < 4; mt++)
                #pragma unroll
                for (int nt = 0; nt < 4; nt++) {
                    mma_bf16(acc[mt][nt], ahi_f[mt], bhi_f[nt]);
                    mma_bf16(acc[mt][nt], ahi_f[mt], blo_f[nt]);
                    mma_bf16(acc[mt][nt], alo_f[mt], bhi_f[nt]);
                }
        }
        __syncthreads();
        int nc = c + NSTAGE;
        if (nc < NC)
            issue_stage(a_hi, a_lo, b_hi, b_lo, K, nc * KC,
                        sbase + (uint32_t)(c % NSTAGE) * STAGE_B, tid);
        CP_COMMIT();
    }

    // epilogue: write from registers, fused bias/res/relu
    int mrow = lane >> 2, ncol = (lane & 3) * 2;
    #pragma unroll
    for (int mt = 0; mt < 4; mt++) {
        #pragma unroll
        for (int nt = 0; nt < 4; nt++) {
            size_t m = (size_t)(m0 + wm + mt * 16 + mrow);
            int n = n0 + wn + nt * 8 + ncol;
            float2 v0 = make_float2(acc[mt][nt][0], acc[mt][nt][1]);
            float2 v1 = make_float2(acc[mt][nt][2], acc[mt][nt][3]);
            if (BIAS) {
                float2 bb = *(const float2*)(bias + n);
                v0.x += bb.x; v0.y += bb.y; v1.x += bb.x; v1.y += bb.y;
            }
            if (RES) {
                float2 r0 = *(const float2*)(res + m * N + n);
                float2 r1 = *(const float2*)(res + (m + 8) * N + n);
                v0.x += r0.x; v0.y += r0.y; v1.x += r1.x; v1.y += r1.y;
            }
            if (RELU) {
                v0.x = fmaxf(v0.x, 0.f); v0.y = fmaxf(v0.y, 0.f);
                v1.x = fmaxf(v1.x, 0.f); v1.y = fmaxf(v1.y, 0.f);
            }
            *(float2*)(C + m * N + n) = v0;
            *(float2*)(C + (m + 8) * N + n) = v1;
        }
    }
}

// ---------------- flash attention (fp32) ----------------
#define ASTR 65

__global__ __launch_bounds__(256) void attn_kernel(
    const float* __restrict__ q, const float* __restrict__ k,
    const float* __restrict__ v, float* __restrict__ o)
{
    float* qs = (float*)g_smem;
    float* ks = qs + 64 * ASTR;
    float* vs = ks + 64 * ASTR;
    float* ps = vs + 64 * ASTR;

    int qt = blockIdx.x, h = blockIdx.y, b = blockIdx.z;
    int tid = threadIdx.x, tx = tid & 15, ty = tid >> 4;
    size_t baseRow = (size_t)b * TLEN;
    int cofs = h * HDIM;

    #pragma unroll
    for (int it = 0; it < 4; it++) {
        int idx = it * 256 + tid;
        int r = idx >> 4, c4 = (idx & 15) * 4;
        float4 d = *(const float4*)(q + (baseRow + qt * 64 + r) * DMODEL + cofs + c4);
        qs[r * ASTR + c4 + 0] = d.x; qs[r * ASTR + c4 + 1] = d.y;
        qs[r * ASTR + c4 + 2] = d.z; qs[r * ASTR + c4 + 3] = d.w;
    }

    float m_i[4], l_i[4], oacc[4][4];
    #pragma unroll
    for (int i = 0; i < 4; i++) {
        m_i[i] = -1e30f; l_i[i] = 0.f;
        #pragma unroll
        for (int j = 0; j < 4; j++) oacc[i][j] = 0.f;
    }

    for (int jt = 0; jt <= qt; jt++) {
        __syncthreads();
        #pragma unroll
        for (int it = 0; it < 4; it++) {
            int idx = it * 256 + tid;
            int r = idx >> 4, c4 = (idx & 15) * 4;
            float4 dk = *(const float4*)(k + (baseRow + jt * 64 + r) * DMODEL + cofs + c4);
            ks[r * ASTR + c4 + 0] = dk.x; ks[r * ASTR + c4 + 1] = dk.y;
            ks[r * ASTR + c4 + 2] = dk.z; ks[r * ASTR + c4 + 3] = dk.w;
            float4 dv = *(const float4*)(v + (baseRow + jt * 64 + r) * DMODEL + cofs + c4);
            vs[r * ASTR + c4 + 0] = dv.x; vs[r * ASTR + c4 + 1] = dv.y;
            vs[r * ASTR + c4 + 2] = dv.z; vs[r * ASTR + c4 + 3] = dv.w;
        }
        __syncthreads();

        float s[4][4];
        #pragma unroll
        for (int i = 0; i < 4; i++)
            #pragma unroll
            for (int j = 0; j < 4; j++) s[i][j] = 0.f;
        for (int d = 0; d < 64; d++) {
            float a[4], bb[4];
            #pragma unroll
            for (int i = 0; i < 4; i++) a[i] = qs[(ty * 4 + i) * ASTR + d];
            #pragma unroll
            for (int j = 0; j < 4; j++) bb[j] = ks[(tx * 4 + j) * ASTR + d];
            #pragma unroll
            for (int i = 0; i < 4; i++)
                #pragma unroll
                for (int j = 0; j < 4; j++) s[i][j] += a[i] * bb[j];
        }
        const float scale = 0.125f;
        #pragma unroll
        for (int i = 0; i < 4; i++)
            #pragma unroll
            for (int j = 0; j < 4; j++) {
                s[i][j] *= scale;
                if (jt == qt && (tx * 4 + j) > (ty * 4 + i)) s[i][j] = -1e30f;
            }

        #pragma unroll
        for (int i = 0; i < 4; i++) {
            float rmax = fmaxf(fmaxf(s[i][0], s[i][1]), fmaxf(s[i][2], s[i][3]));
            #pragma unroll
            for (int off = 8; off; off >>= 1)
                rmax = fmaxf(rmax, __shfl_xor_sync(0xffffffffu, rmax, off, 16));
            float mnew = fmaxf(m_i[i], rmax);
            float alpha = __expf(m_i[i] - mnew);
            float rsum = 0.f;
            #pragma unroll
            for (int j = 0; j < 4; j++) {
                s[i][j] = __expf(s[i][j] - mnew);
                rsum += s[i][j];
            }
            #pragma unroll
            for (int off = 8; off; off >>= 1)
                rsum += __shfl_xor_sync(0xffffffffu, rsum, off, 16);
            l_i[i] = l_i[i] * alpha + rsum;
            m_i[i] = mnew;
            #pragma unroll
            for (int j = 0; j < 4; j++) oacc[i][j] *= alpha;
            #pragma unroll
            for (int j = 0; j < 4; j++)
                ps[(ty * 4 + i) * ASTR + tx * 4 + j] = s[i][j];
        }
        __syncthreads();

        for (int kc = 0; kc < 64; kc++) {
            float a[4], bb[4];
            #pragma unroll
            for (int i = 0; i < 4; i++) a[i] = ps[(ty * 4 + i) * ASTR + kc];
            #pragma unroll
            for (int j = 0; j < 4; j++) bb[j] = vs[kc * ASTR + tx * 4 + j];
            #pragma unroll
            for (int i = 0; i < 4; i++)
                #pragma unroll
                for (int j = 0; j < 4; j++) oacc[i][j] += a[i] * bb[j];
        }
    }

    #pragma unroll
    for (int i = 0; i < 4; i++) {
        float invl = 1.f / l_i[i];
        size_t row = baseRow + qt * 64 + ty * 4 + i;
        #pragma unroll
        for (int j = 0; j < 4; j++)
            o[row * DMODEL + cofs + tx * 4 + j] = oacc[i][j] * invl;
    }
}

// ---------------- launcher ----------------
extern "C" void kernel_launch(void* const* d_in, const int* in_sizes, int n_in,
                              void* d_out, int out_size)
{
    const int*   idx  = (const int*)d_in[0];
    const float* tok  = (const float*)d_in[1];
    const float* pos  = (const float*)d_in[2];
    const float* Wq   = (const float*)d_in[3];
    const float* Wk   = (const float*)d_in[4];
    const float* Wv   = (const float*)d_in[5];
    const float* Wo   = (const float*)d_in[6];
    const float* bo   = (const float*)d_in[7];
    const float* ln1g = (const float*)d_in[8];
    const float* ln1b = (const float*)d_in[9];
    const float* ln2g = (const float*)d_in[10];
    const float* ln2b = (const float*)d_in[11];
    const float* W1   = (const float*)d_in[12];
    const float* b1   = (const float*)d_in[13];
    const float* W2   = (const float*)d_in[14];
    const float* b2   = (const float*)d_in[15];
    const float* lnfg = (const float*)d_in[16];
    const float* lnfb = (const float*)d_in[17];
    const float* Wh   = (const float*)d_in[18];
    const float* bh   = (const float*)d_in[19];
    float* out = (float*)d_out;

    float *x, *h, *q, *k, *v, *attn, *ff;
    __nv_bfloat16 *ahi, *alo, *wbuf;
    cudaGetSymbolAddress((void**)&x, g_x);
    cudaGetSymbolAddress((void**)&h, g_h);
    cudaGetSymbolAddress((void**)&q, g_q);
    cudaGetSymbolAddress((void**)&k, g_k);
    cudaGetSymbolAddress((void**)&v, g_v);
    cudaGetSymbolAddress((void**)&attn, g_attn);
    cudaGetSymbolAddress((void**)&ff, g_ff);
    cudaGetSymbolAddress((void**)&ahi, g_act_hi);
    cudaGetSymbolAddress((void**)&alo, g_act_lo);
    cudaGetSymbolAddress((void**)&wbuf, g_wbuf);

    const int attn_smem = 4 * 64 * ASTR * sizeof(float);
    cudaFuncSetAttribute(attn_kernel, cudaFuncAttributeMaxDynamicSharedMemorySize, attn_smem);
    cudaFuncSetAttribute(gemm_tc_kernel<false,false,false>, cudaFuncAttributeMaxDynamicSharedMemorySize, GEMM_SMEM);
    cudaFuncSetAttribute(gemm_tc_kernel<true,false,true>,  cudaFuncAttributeMaxDynamicSharedMemorySize, GEMM_SMEM);
    cudaFuncSetAttribute(gemm_tc_kernel<true,true,false>,  cudaFuncAttributeMaxDynamicSharedMemorySize, GEMM_SMEM);
    cudaFuncSetAttribute(gemm_tc_kernel<true,false,false>, cudaFuncAttributeMaxDynamicSharedMemorySize, GEMM_SMEM);

    // ---- weight conversion (transposed bf16 hi/lo) ----
    const size_t M1 = 1048576, M4 = 4194304;
    const size_t layer_elems = 2 * (4 * M1 + 2 * M4);
    __nv_bfloat16* wh_hi = wbuf + 6 * layer_elems;
    __nv_bfloat16* wh_lo = wh_hi + (size_t)VOCAB * DMODEL;

    dim3 cblk(32, 8);
    for (int l = 0; l < NLAYER; l++) {
        __nv_bfloat16* base = wbuf + l * layer_elems;
        __nv_bfloat16* wq_hi = base;            __nv_bfloat16* wq_lo = base + M1;
        __nv_bfloat16* wk_hi = base + 2*M1;     __nv_bfloat16* wk_lo = base + 3*M1;
        __nv_bfloat16* wv_hi = base + 4*M1;     __nv_bfloat16* wv_lo = base + 5*M1;
        __nv_bfloat16* wo_hi = base + 6*M1;     __nv_bfloat16* wo_lo = base + 7*M1;
        __nv_bfloat16* w1_hi = base + 8*M1;     __nv_bfloat16* w1_lo = w1_hi + M4;
        __nv_bfloat16* w2_hi = w1_hi + 2*M4;    __nv_bfloat16* w2_lo = w2_hi + M4;

        convw_kernel<true><<<dim3(32,32), cblk>>>(Wq + l*M1, wq_hi, wq_lo, DMODEL, DMODEL);
        convw_kernel<true><<<dim3(32,32), cblk>>>(Wk + l*M1, wk_hi, wk_lo, DMODEL, DMODEL);
        convw_kernel<true><<<dim3(32,32), cblk>>>(Wv + l*M1, wv_hi, wv_lo, DMODEL, DMODEL);
        convw_kernel<false><<<dim3(32,32), cblk>>>(Wo + l*M1, wo_hi, wo_lo, DMODEL, DMODEL);
        convw_kernel<false><<<dim3(128,32), cblk>>>(W1 + l*M4, w1_hi, w1_lo, DMODEL, DFF);
        convw_kernel<false><<<dim3(32,128), cblk>>>(W2 + l*M4, w2_hi, w2_lo, DFF, DMODEL);
    }
    convw_kernel<false><<<dim3(VOCAB/32, 32), cblk>>>(Wh, wh_hi, wh_lo, DMODEL, VOCAB);

    // ---- forward ----
    embed_kernel<<<NROWS, 256>>>(idx, tok, pos, x);

    dim3 gD(DMODEL/BN, NROWS/BM);     // 8 x 16
    dim3 gF(DFF/BN, NROWS/BM);        // 32 x 16
    dim3 gV(VOCAB/BN, NROWS/BM);      // 250 x 16
    const int nD4 = NROWS * DMODEL / 4, nF4 = NROWS * DFF / 4;

    for (int l = 0; l < NLAYER; l++) {
        __nv_bfloat16* base = wbuf + l * layer_elems;
        __nv_bfloat16* wq_hi = base;            __nv_bfloat16* wq_lo = base + M1;
        __nv_bfloat16* wk_hi = base + 2*M1;     __nv_bfloat16* wk_lo = base + 3*M1;
        __nv_bfloat16* wv_hi = base + 4*M1;     __nv_bfloat16* wv_lo = base + 5*M1;
        __nv_bfloat16* wo_hi = base + 6*M1;     __nv_bfloat16* wo_lo = base + 7*M1;
        __nv_bfloat16* w1_hi = base + 8*M1;     __nv_bfloat16* w1_lo = w1_hi + M4;
        __nv_bfloat16* w2_hi = w1_hi + 2*M4;    __nv_bfloat16* w2_lo = w2_hi + M4;

        ln_kernel<<<NROWS, 256>>>(x, ln1g + l*DMODEL, ln1b + l*DMODEL, h);
        convact_kernel<<<nD4/256, 256>>>(h, ahi, alo);
        gemm_tc_kernel<false,false,false><<<gD, 256, GEMM_SMEM>>>(
            ahi, alo, wq_hi, wq_lo, nullptr, nullptr, q, DMODEL, DMODEL);
        gemm_tc_kernel<false,false,false><<<gD, 256, GEMM_SMEM>>>(
            ahi, alo, wk_hi, wk_lo, nullptr, nullptr, k, DMODEL, DMODEL);
        gemm_tc_kernel<false,false,false><<<gD, 256, GEMM_SMEM>>>(
            ahi, alo, wv_hi, wv_lo, nullptr, nullptr, v, DMODEL, DMODEL);

        attn_kernel<<<dim3(TLEN/64, NHEAD, BATCH), 256, attn_smem>>>(q, k, v, attn);

        convact_kernel<<<nD4/256, 256>>>(attn, ahi, alo);
        gemm_tc_kernel<true,false,true><<<gD, 256, GEMM_SMEM>>>(
            ahi, alo, wo_hi, wo_lo, bo + l*DMODEL, x, x, DMODEL, DMODEL);

        ln_kernel<<<NROWS, 256>>>(x, ln2g + l*DMODEL, ln2b + l*DMODEL, h);
        convact_kernel<<<nD4/256, 256>>>(h, ahi, alo);
        gemm_tc_kernel<true,true,false><<<gF, 256, GEMM_SMEM>>>(
            ahi, alo, w1_hi, w1_lo, b1 + (size_t)l*DFF, nullptr, ff, DFF, DMODEL);

        convact_kernel<<<nF4/256, 256>>>(ff, ahi, alo);
        gemm_tc_kernel<true,false,true><<<gD, 256, GEMM_SMEM>>>(
            ahi, alo, w2_hi, w2_lo, b2 + l*DMODEL, x, x, DMODEL, DFF);
    }

    ln_kernel<<<NROWS, 256>>>(x, lnfg, lnfb, h);
    convact_kernel<<<nD4/256, 256>>>(h, ahi, alo);
    gemm_tc_kernel<true,false,false><<<gV, 256, GEMM_SMEM>>>(
        ahi, alo, wh_hi, wh_lo, bh, nullptr, out, VOCAB, DMODEL);
}

// round 5
// speedup vs baseline: 3.2454x; 1.2429x over previous
#include <cuda_runtime.h>
#include <cuda_bf16.h>
#include <math.h>
#include <stdint.h>

// ---------------- problem constants ----------------
#define BATCH 2
#define TLEN  1024
#define DMODEL 1024
#define NHEAD 16
#define HDIM 64
#define NLAYER 6
#define VOCAB 32000
#define DFF 4096
#define NROWS (BATCH*TLEN)   // 2048

// ---------------- scratch (device globals) ----------------
__device__ float g_x[NROWS*DMODEL];
__device__ __nv_bfloat16 g_hhi[NROWS*DMODEL],  g_hlo[NROWS*DMODEL];
__device__ __nv_bfloat16 g_qhi[NROWS*DMODEL],  g_qlo[NROWS*DMODEL];
__device__ __nv_bfloat16 g_khi[NROWS*DMODEL],  g_klo[NROWS*DMODEL];
__device__ __nv_bfloat16 g_vhi[NROWS*DMODEL],  g_vlo[NROWS*DMODEL];
__device__ __nv_bfloat16 g_atthi[NROWS*DMODEL],g_attlo[NROWS*DMODEL];
__device__ __nv_bfloat16 g_ffhi[NROWS*DFF],    g_fflo[NROWS*DFF];

// converted transposed weights arena (bf16 hi/lo)
#define WARENA_ELEMS (2ull*(6ull*(4ull*1048576ull + 2ull*4194304ull) + 32768000ull))
__device__ __nv_bfloat16 g_wbuf[WARENA_ELEMS];

extern __shared__ __align__(1024) char g_smem[];

// ================= PTX helpers =================
__device__ __forceinline__ uint32_t smem_u32(const void* p) {
    uint32_t a;
    asm("{ .reg .u64 t; cvta.to.shared.u64 t, %1; cvt.u32.u64 %0, t; }" : "=r"(a) : "l"(p));
    return a;
}
__device__ __forceinline__ void cp_async16(uint32_t sm, const void* g) {
    asm volatile("cp.async.cg.shared.global [%0], [%1], 16;" :: "r"(sm), "l"(g) : "memory");
}
#define CP_COMMIT() asm volatile("cp.async.commit_group;" ::: "memory")
#define CP_WAIT2()  asm volatile("cp.async.wait_group 2;" ::: "memory")
#define CP_WAIT0()  asm volatile("cp.async.wait_group 0;" ::: "memory")

__device__ __forceinline__ void ldsm4(uint32_t* r, uint32_t addr) {
    asm volatile("ldmatrix.sync.aligned.m8n8.x4.shared.b16 {%0,%1,%2,%3}, [%4];"
        : "=r"(r[0]), "=r"(r[1]), "=r"(r[2]), "=r"(r[3]) : "r"(addr));
}
__device__ __forceinline__ void ldsm4t(uint32_t* r, uint32_t addr) {
    asm volatile("ldmatrix.sync.aligned.m8n8.x4.trans.shared.b16 {%0,%1,%2,%3}, [%4];"
        : "=r"(r[0]), "=r"(r[1]), "=r"(r[2]), "=r"(r[3]) : "r"(addr));
}
__device__ __forceinline__ void mma_bf16(float* c, const uint32_t* a, const uint32_t* b) {
    asm volatile(
        "mma.sync.aligned.m16n8k16.row.col.f32.bf16.bf16.f32 "
        "{%0,%1,%2,%3}, {%4,%5,%6,%7}, {%8,%9}, {%0,%1,%2,%3};"
        : "+f"(c[0]), "+f"(c[1]), "+f"(c[2]), "+f"(c[3])
        : "r"(a[0]), "r"(a[1]), "r"(a[2]), "r"(a[3]), "r"(b[0]), "r"(b[1]));
}

#define SW128(off) ((off) ^ (((off) >> 3) & 0x70))

// ---------------- splits ----------------
__device__ __forceinline__ void split_bf16(float x, __nv_bfloat16& h, __nv_bfloat16& l)
{
    h = __float2bfloat16(x);
    l = __float2bfloat16(x - __bfloat162float(h));
}
__device__ __forceinline__ void split2pack(float x, float y, uint32_t& hi, uint32_t& lo)
{
    __nv_bfloat16 hx, lx, hy, ly;
    split_bf16(x, hx, lx); split_bf16(y, hy, ly);
    __nv_bfloat162 hv(hx, hy), lv(lx, ly);
    hi = *(uint32_t*)&hv;
    lo = *(uint32_t*)&lv;
}

// ---------------- embed ----------------
__global__ __launch_bounds__(256) void embed_kernel(
    const int* __restrict__ idx, const float* __restrict__ tok,
    const float* __restrict__ pos, float* __restrict__ x)
{
    int i = blockIdx.x * blockDim.x + threadIdx.x;
    int row = i >> 8;
    int c4  = (i & 255) * 4;
    int t = row & (TLEN - 1);
    int token = idx[row];
    float4 a = *(const float4*)(tok + (size_t)token * DMODEL + c4);
    float4 p = *(const float4*)(pos + (size_t)t * DMODEL + c4);
    float4 o; o.x = a.x + p.x; o.y = a.y + p.y; o.z = a.z + p.z; o.w = a.w + p.w;
    *(float4*)(x + (size_t)row * DMODEL + c4) = o;
}

// ---------------- layernorm -> bf16 hi/lo ----------------
__device__ __forceinline__ float block_sum256(float v, float* sbuf)
{
    #pragma unroll
    for (int o = 16; o; o >>= 1) v += __shfl_xor_sync(0xffffffffu, v, o);
    int w = threadIdx.x >> 5;
    if ((threadIdx.x & 31) == 0) sbuf[w] = v;
    __syncthreads();
    if (threadIdx.x < 32) {
        float r = (threadIdx.x < 8) ? sbuf[threadIdx.x] : 0.f;
        #pragma unroll
        for (int o = 4; o; o >>= 1) r += __shfl_xor_sync(0xffffffffu, r, o);
        if (threadIdx.x == 0) sbuf[0] = r;
    }
    __syncthreads();
    float out = sbuf[0];
    __syncthreads();
    return out;
}

__global__ __launch_bounds__(256) void ln_split_kernel(
    const float* __restrict__ x, const float* __restrict__ g,
    const float* __restrict__ b, __nv_bfloat16* __restrict__ hi,
    __nv_bfloat16* __restrict__ lo)
{
    __shared__ float sbuf[8];
    size_t row = blockIdx.x;
    const float* xr = x + row * DMODEL;
    int c = threadIdx.x * 4;
    float4 d = *(const float4*)(xr + c);
    float mean = block_sum256(d.x + d.y + d.z + d.w, sbuf) * (1.f / DMODEL);
    float ex = d.x - mean, ey = d.y - mean, ez = d.z - mean, ew = d.w - mean;
    float var = block_sum256(ex*ex + ey*ey + ez*ez + ew*ew, sbuf) * (1.f / DMODEL);
    float inv = rsqrtf(var + 1e-5f);
    float4 gg = *(const float4*)(g + c);
    float4 bb = *(const float4*)(b + c);
    float ox = ex * inv * gg.x + bb.x;
    float oy = ey * inv * gg.y + bb.y;
    float oz = ez * inv * gg.z + bb.z;
    float ow = ew * inv * gg.w + bb.w;
    uint32_t h0, l0, h1, l1;
    split2pack(ox, oy, h0, l0);
    split2pack(oz, ow, h1, l1);
    *(uint2*)(hi + row * DMODEL + c) = make_uint2(h0, h1);
    *(uint2*)(lo + row * DMODEL + c) = make_uint2(l0, l1);
}

// ---------------- weight transpose + split ----------------
template<bool HEADB>
__global__ __launch_bounds__(256) void convw_kernel(
    const float* __restrict__ W, __nv_bfloat16* __restrict__ hi,
    __nv_bfloat16* __restrict__ lo, int K, int N)
{
    __shared__ float sm[32][33];
    int tx = threadIdx.x, ty = threadIdx.y;
    int n0 = blockIdx.x * 32, k0 = blockIdx.y * 32;
    #pragma unroll
    for (int i = 0; i < 4; i++) {
        int k = k0 + ty + i * 8, n = n0 + tx;
        size_t addr = HEADB ? ((size_t)(n >> 6) * (DMODEL * HDIM) + (size_t)k * HDIM + (n & 63))
                            : ((size_t)k * N + n);
        sm[ty + i * 8][tx] = W[addr];
    }
    __syncthreads();
    #pragma unroll
    for (int i = 0; i < 4; i++) {
        int n = n0 + ty + i * 8, k = k0 + tx;
        float v = sm[tx][ty + i * 8];
        __nv_bfloat16 h, l;
        split_bf16(v, h, l);
        hi[(size_t)n * K + k] = h;
        lo[(size_t)n * K + k] = l;
    }
}

// ---------------- mma.sync GEMM (bf16x3) ----------------
#define BM 128
#define BN 128
#define KC 64
#define NSTAGE 3
#define TILE_B 16384
#define STAGE_B (4*TILE_B)
#define GEMM_SMEM (NSTAGE*STAGE_B)   // 196608

__device__ __forceinline__ void issue_stage(
    const __nv_bfloat16* __restrict__ a_hi, const __nv_bfloat16* __restrict__ a_lo,
    const __nv_bfloat16* __restrict__ b_hi, const __nv_bfloat16* __restrict__ b_lo,
    int K, int k0, uint32_t st_addr, int tid)
{
    const __nv_bfloat16* srcs[4] = { a_hi + k0, a_lo + k0, b_hi + k0, b_lo + k0 };
    #pragma unroll
    for (int t = 0; t < 4; t++) {
        const __nv_bfloat16* g = srcs[t];
        uint32_t sm = st_addr + t * TILE_B;
        #pragma unroll
        for (int i = 0; i < 4; i++) {
            int idx = i * 256 + tid;
            int r = idx >> 3, u = idx & 7;
            const void* gp = (const char*)(g + (size_t)r * K) + u * 16;
            uint32_t off = (uint32_t)(r * 128 + u * 16);
            cp_async16(sm + SW128(off), gp);
        }
    }
}

template<bool BIAS, bool RELU, bool RES, bool SPLIT>
__global__ __launch_bounds__(256) void gemm_tc_kernel(
    const __nv_bfloat16* __restrict__ Ahi, const __nv_bfloat16* __restrict__ Alo,
    const __nv_bfloat16* __restrict__ Bhi, const __nv_bfloat16* __restrict__ Blo,
    const float* __restrict__ bias, const float* __restrict__ res,
    float* __restrict__ C, __nv_bfloat16* __restrict__ Chi,
    __nv_bfloat16* __restrict__ Clo, int N, int K)
{
    uint32_t sbase = smem_u32(g_smem);
    int tid = threadIdx.x, lane = tid & 31, wid = tid >> 5;
    int n0 = blockIdx.x * BN, m0 = blockIdx.y * BM;
    int wm = (wid & 1) * 64, wn = (wid >> 1) * 32;
    int NC = K / KC;

    const __nv_bfloat16* a_hi = Ahi + (size_t)m0 * K;
    const __nv_bfloat16* a_lo = Alo + (size_t)m0 * K;
    const __nv_bfloat16* b_hi = Bhi + (size_t)n0 * K;
    const __nv_bfloat16* b_lo = Blo + (size_t)n0 * K;

    float acc[4][4][4];
    #pragma unroll
    for (int i = 0; i < 4; i++)
        #pragma unroll
        for (int j = 0; j < 4; j++)
            #pragma unroll
            for (int r = 0; r < 4; r++) acc[i][j][r] = 0.f;

    #pragma unroll
    for (int s = 0; s < NSTAGE; s++) {
        issue_stage(a_hi, a_lo, b_hi, b_lo, K, s * KC, sbase + s * STAGE_B, tid);
        CP_COMMIT();
    }

    int aq = lane >> 4;
    int arow_l = lane & 15;
    uint32_t a_sw = (uint32_t)((arow_l & 7) << 4);
    int bq = lane >> 3;
    int brow_l = lane & 7;
    uint32_t b_sw = (uint32_t)(brow_l << 4);
    uint32_t a_colb0 = (uint32_t)(aq * 16);
    uint32_t b_colb0 = (uint32_t)((bq & 1) * 16);
    int b_rowloc = (bq >> 1) * 8 + brow_l;

    for (int c = 0; c < NC; c++) {
        CP_WAIT2();
        __syncthreads();
        uint32_t st = sbase + (uint32_t)(c % NSTAGE) * STAGE_B;
        uint32_t stA_hi = st, stA_lo = st + TILE_B;
        uint32_t stB_hi = st + 2 * TILE_B, stB_lo = st + 3 * TILE_B;

        #pragma unroll
        for (int ks = 0; ks < 4; ks++) {
            uint32_t a_colb = (uint32_t)(ks * 32) + a_colb0;
            uint32_t b_colb = (uint32_t)(ks * 32) + b_colb0;
            uint32_t ahi_f[4][4], alo_f[4][4], bhi_f[4][2], blo_f[4][2];
            #pragma unroll
            for (int mt = 0; mt < 4; mt++) {
                uint32_t ro = (uint32_t)((wm + mt * 16 + arow_l) * 128);
                ldsm4(ahi_f[mt], stA_hi + ro + (a_colb ^ a_sw));
                ldsm4(alo_f[mt], stA_lo + ro + (a_colb ^ a_sw));
            }
            #pragma unroll
            for (int np = 0; np < 2; np++) {
                uint32_t ro = (uint32_t)((wn + np * 16 + b_rowloc) * 128);
                uint32_t r4[4];
                ldsm4(r4, stB_hi + ro + (b_colb ^ b_sw));
                bhi_f[np*2][0] = r4[0]; bhi_f[np*2][1] = r4[1];
                bhi_f[np*2+1][0] = r4[2]; bhi_f[np*2+1][1] = r4[3];
                ldsm4(r4, stB_lo + ro + (b_colb ^ b_sw));
                blo_f[np*2][0] = r4[0]; blo_f[np*2][1] = r4[1];
                blo_f[np*2+1][0] = r4[2]; blo_f[np*2+1][1] = r4[3];
            }
            #pragma unroll
            for (int mt = 0; mt < 4; mt++)
                #pragma unroll
                for (int nt = 0; nt < 4; nt++) {
                    mma_bf16(acc[mt][nt], ahi_f[mt], bhi_f[nt]);
                    mma_bf16(acc[mt][nt], ahi_f[mt], blo_f[nt]);
                    mma_bf16(acc[mt][nt], alo_f[mt], bhi_f[nt]);
                }
        }
        __syncthreads();
        int nc = c + NSTAGE;
        if (nc < NC)
            issue_stage(a_hi, a_lo, b_hi, b_lo, K, nc * KC,
                        sbase + (uint32_t)(c % NSTAGE) * STAGE_B, tid);
        CP_COMMIT();
    }

    int mrow = lane >> 2, ncol = (lane & 3) * 2;
    #pragma unroll
    for (int mt = 0; mt < 4; mt++) {
        #pragma unroll
        for (int nt = 0; nt < 4; nt++) {
            size_t m = (size_t)(m0 + wm + mt * 16 + mrow);
            int n = n0 + wn + nt * 8 + ncol;
            float2 v0 = make_float2(acc[mt][nt][0], acc[mt][nt][1]);
            float2 v1 = make_float2(acc[mt][nt][2], acc[mt][nt][3]);
            if (BIAS) {
                float2 bb = *(const float2*)(bias + n);
                v0.x += bb.x; v0.y += bb.y; v1.x += bb.x; v1.y += bb.y;
            }
            if (RES) {
                float2 r0 = *(const float2*)(res + m * N + n);
                float2 r1 = *(const float2*)(res + (m + 8) * N + n);
                v0.x += r0.x; v0.y += r0.y; v1.x += r1.x; v1.y += r1.y;
            }
            if (RELU) {
                v0.x = fmaxf(v0.x, 0.f); v0.y = fmaxf(v0.y, 0.f);
                v1.x = fmaxf(v1.x, 0.f); v1.y = fmaxf(v1.y, 0.f);
            }
            if (SPLIT) {
                uint32_t hh, ll;
                split2pack(v0.x, v0.y, hh, ll);
                *(uint32_t*)(Chi + m * N + n) = hh;
                *(uint32_t*)(Clo + m * N + n) = ll;
                split2pack(v1.x, v1.y, hh, ll);
                *(uint32_t*)(Chi + (m + 8) * N + n) = hh;
                *(uint32_t*)(Clo + (m + 8) * N + n) = ll;
            } else {
                *(float2*)(C + m * N + n) = v0;
                *(float2*)(C + (m + 8) * N + n) = v1;
            }
        }
    }
}

// ---------------- tensor-core flash attention (bf16x3) ----------------
// 128 threads = 4 warps; warp w: 16 q-rows. Tiles 64x64, HD=64.
#define ATT_SMEM (6*8192)   // Qhi Qlo Khi Klo Vhi Vlo

__global__ __launch_bounds__(128) void attn_tc_kernel(
    const __nv_bfloat16* __restrict__ Qhi, const __nv_bfloat16* __restrict__ Qlo,
    const __nv_bfloat16* __restrict__ Khi, const __nv_bfloat16* __restrict__ Klo,
    const __nv_bfloat16* __restrict__ Vhi, const __nv_bfloat16* __restrict__ Vlo,
    __nv_bfloat16* __restrict__ Ohi, __nv_bfloat16* __restrict__ Olo)
{
    uint32_t sb = smem_u32(g_smem);
    uint32_t sQh = sb, sQl = sb + 8192, sKh = sb + 16384, sKl = sb + 24576,
             sVh = sb + 32768, sVl = sb + 40960;
    int qt = blockIdx.x, h = blockIdx.y, b = blockIdx.z;
    int tid = threadIdx.x, lane = tid & 31, w = tid >> 5;
    size_t rowbase = (size_t)b * TLEN;
    int cofs = h * HDIM;

    // Q tile load (hi, lo)
    {
        const __nv_bfloat16* qh = Qhi + (rowbase + qt * 64) * DMODEL + cofs;
        const __nv_bfloat16* ql = Qlo + (rowbase + qt * 64) * DMODEL + cofs;
        #pragma unroll
        for (int i = 0; i < 4; i++) {
            int idx = i * 128 + tid;
            int r = idx >> 3, u = idx & 7;
            uint32_t off = SW128((uint32_t)(r * 128 + u * 16));
            cp_async16(sQh + off, qh + (size_t)r * DMODEL + u * 8);
            cp_async16(sQl + off, ql + (size_t)r * DMODEL + u * 8);
        }
        CP_COMMIT();
    }

    float m0r = -1e30f, m1r = -1e30f, l0r = 0.f, l1r = 0.f;
    float o[8][4];
    #pragma unroll
    for (int e = 0; e < 8; e++)
        #pragma unroll
        for (int r = 0; r < 4; r++) o[e][r] = 0.f;

    int g = lane >> 2;               // row-in-16 group
    int c2 = (lane & 3) * 2;         // col pair base
    uint32_t a_sw = (uint32_t)((lane & 7) << 4);
    int aq = lane >> 4, arow_l = lane & 15;
    int bq = lane >> 3, brow_l = lane & 7;
    int b_rowloc = (bq >> 1) * 8 + brow_l;
    uint32_t b_colsel = (uint32_t)((bq & 1) * 16);

    for (int jt = 0; jt <= qt; jt++) {
        __syncthreads();
        // load K/V tiles
        {
            const __nv_bfloat16* kh = Khi + (rowbase + jt * 64) * DMODEL + cofs;
            const __nv_bfloat16* kl = Klo + (rowbase + jt * 64) * DMODEL + cofs;
            const __nv_bfloat16* vh = Vhi + (rowbase + jt * 64) * DMODEL + cofs;
            const __nv_bfloat16* vl = Vlo + (rowbase + jt * 64) * DMODEL + cofs;
            #pragma unroll
            for (int i = 0; i < 4; i++) {
                int idx = i * 128 + tid;
                int r = idx >> 3, u = idx & 7;
                uint32_t off = SW128((uint32_t)(r * 128 + u * 16));
                size_t go = (size_t)r * DMODEL + u * 8;
                cp_async16(sKh + off, kh + go);
                cp_async16(sKl + off, kl + go);
                cp_async16(sVh + off, vh + go);
                cp_async16(sVl + off, vl + go);
            }
            CP_COMMIT();
            CP_WAIT0();
            __syncthreads();
        }

        // S = Q K^T (bf16x3)
        float s[8][4];
        #pragma unroll
        for (int nt = 0; nt < 8; nt++)
            #pragma unroll
            for (int r = 0; r < 4; r++) s[nt][r] = 0.f;

        #pragma unroll
        for (int ks = 0; ks < 4; ks++) {
            uint32_t qh_f[4], ql_f[4];
            uint32_t ro = (uint32_t)((w * 16 + arow_l) * 128);
            uint32_t cb = (uint32_t)(ks * 32 + aq * 16);
            ldsm4(qh_f, sQh + ro + (cb ^ a_sw));
            ldsm4(ql_f, sQl + ro + (cb ^ a_sw));
            #pragma unroll
            for (int np = 0; np < 4; np++) {
                uint32_t rk = (uint32_t)((np * 16 + b_rowloc) * 128);
                uint32_t cbk = (uint32_t)(ks * 32) + b_colsel;
                uint32_t swk = (uint32_t)(brow_l << 4);
                uint32_t kh4[4], kl4[4];
                ldsm4(kh4, sKh + rk + (cbk ^ swk));
                ldsm4(kl4, sKl + rk + (cbk ^ swk));
                uint32_t bh0[2] = {kh4[0], kh4[1]}, bh1[2] = {kh4[2], kh4[3]};
                uint32_t bl0[2] = {kl4[0], kl4[1]}, bl1[2] = {kl4[2], kl4[3]};
                mma_bf16(s[2*np],   qh_f, bh0);
                mma_bf16(s[2*np],   qh_f, bl0);
                mma_bf16(s[2*np],   ql_f, bh0);
                mma_bf16(s[2*np+1], qh_f, bh1);
                mma_bf16(s[2*np+1], qh_f, bl1);
                mma_bf16(s[2*np+1], ql_f, bh1);
            }
        }

        // scale + causal mask
        const float scale = 0.125f;
        #pragma unroll
        for (int nt = 0; nt < 8; nt++)
            #pragma unroll
            for (int r = 0; r < 4; r++) s[nt][r] *= scale;
        if (jt == qt) {
            int row0 = w * 16 + g, row1 = row0 + 8;
            #pragma unroll
            for (int nt = 0; nt < 8; nt++) {
                int cc = nt * 8 + c2;
                if (cc     > row0) s[nt][0] = -1e30f;
                if (cc + 1 > row0) s[nt][1] = -1e30f;
                if (cc     > row1) s[nt][2] = -1e30f;
                if (cc + 1 > row1) s[nt][3] = -1e30f;
            }
        }

        // online softmax (rows g, g+8)
        float mx0 = -1e30f, mx1 = -1e30f;
        #pragma unroll
        for (int nt = 0; nt < 8; nt++) {
            mx0 = fmaxf(mx0, fmaxf(s[nt][0], s[nt][1]));
            mx1 = fmaxf(mx1, fmaxf(s[nt][2], s[nt][3]));
        }
        mx0 = fmaxf(mx0, __shfl_xor_sync(0xffffffffu, mx0, 1));
        mx0 = fmaxf(mx0, __shfl_xor_sync(0xffffffffu, mx0, 2));
        mx1 = fmaxf(mx1, __shfl_xor_sync(0xffffffffu, mx1, 1));
        mx1 = fmaxf(mx1, __shfl_xor_sync(0xffffffffu, mx1, 2));
        float mn0 = fmaxf(m0r, mx0), mn1 = fmaxf(m1r, mx1);
        float al0 = __expf(m0r - mn0), al1 = __expf(m1r - mn1);
        float sm0 = 0.f, sm1 = 0.f;
        #pragma unroll
        for (int nt = 0; nt < 8; nt++) {
            s[nt][0] = __expf(s[nt][0] - mn0);
            s[nt][1] = __expf(s[nt][1] - mn0);
            s[nt][2] = __expf(s[nt][2] - mn1);
            s[nt][3] = __expf(s[nt][3] - mn1);
            sm0 += s[nt][0] + s[nt][1];
            sm1 += s[nt][2] + s[nt][3];
        }
        sm0 += __shfl_xor_sync(0xffffffffu, sm0, 1);
        sm0 += __shfl_xor_sync(0xffffffffu, sm0, 2);
        sm1 += __shfl_xor_sync(0xffffffffu, sm1, 1);
        sm1 += __shfl_xor_sync(0xffffffffu, sm1, 2);
        l0r = l0r * al0 + sm0;
        l1r = l1r * al1 + sm1;
        m0r = mn0; m1r = mn1;
        #pragma unroll
        for (int e = 0; e < 8; e++) {
            o[e][0] *= al0; o[e][1] *= al0;
            o[e][2] *= al1; o[e][3] *= al1;
        }

        // O += P V (bf16x3); P fragments built in-register
        #pragma unroll
        for (int ks = 0; ks < 4; ks++) {
            uint32_t pa_h[4], pa_l[4];
            split2pack(s[2*ks][0],   s[2*ks][1],   pa_h[0], pa_l[0]);
            split2pack(s[2*ks][2],   s[2*ks][3],   pa_h[1], pa_l[1]);
            split2pack(s[2*ks+1][0], s[2*ks+1][1], pa_h[2], pa_l[2]);
            split2pack(s[2*ks+1][2], s[2*ks+1][3], pa_h[3], pa_l[3]);
            #pragma unroll
            for (int np = 0; np < 4; np++) {
                uint32_t srow = (uint32_t)(ks * 16 + (bq & 1) * 8 + brow_l);
                uint32_t cbv = (uint32_t)(np * 32 + (bq >> 1) * 16);
                uint32_t swv = (uint32_t)(brow_l << 4);
                uint32_t vh4[4], vl4[4];
                ldsm4t(vh4, sVh + srow * 128 + (cbv ^ swv));
                ldsm4t(vl4, sVl + srow * 128 + (cbv ^ swv));
                uint32_t bh0[2] = {vh4[0], vh4[1]}, bh1[2] = {vh4[2], vh4[3]};
                uint32_t bl0[2] = {vl4[0], vl4[1]}, bl1[2] = {vl4[2], vl4[3]};
                mma_bf16(o[2*np],   pa_h, bh0);
                mma_bf16(o[2*np],   pa_h, bl0);
                mma_bf16(o[2*np],   pa_l, bh0);
                mma_bf16(o[2*np+1], pa_h, bh1);
                mma_bf16(o[2*np+1], pa_h, bl1);
                mma_bf16(o[2*np+1], pa_l, bh1);
            }
        }
    }

    // normalize + write (bf16 hi/lo split)
    float inv0 = 1.f / l0r, inv1 = 1.f / l1r;
    size_t r0 = rowbase + qt * 64 + w * 16 + g;
    size_t r1 = r0 + 8;
    #pragma unroll
    for (int e = 0; e < 8; e++) {
        int n = cofs + e * 8 + c2;
        uint32_t hh, ll;
        split2pack(o[e][0] * inv0, o[e][1] * inv0, hh, ll);
        *(uint32_t*)(Ohi + r0 * DMODEL + n) = hh;
        *(uint32_t*)(Olo + r0 * DMODEL + n) = ll;
        split2pack(o[e][2] * inv1, o[e][3] * inv1, hh, ll);
        *(uint32_t*)(Ohi + r1 * DMODEL + n) = hh;
        *(uint32_t*)(Olo + r1 * DMODEL + n) = ll;
    }
}

// ---------------- launcher ----------------
extern "C" void kernel_launch(void* const* d_in, const int* in_sizes, int n_in,
                              void* d_out, int out_size)
{
    const int*   idx  = (const int*)d_in[0];
    const float* tok  = (const float*)d_in[1];
    const float* pos  = (const float*)d_in[2];
    const float* Wq   = (const float*)d_in[3];
    const float* Wk   = (const float*)d_in[4];
    const float* Wv   = (const float*)d_in[5];
    const float* Wo   = (const float*)d_in[6];
    const float* bo   = (const float*)d_in[7];
    const float* ln1g = (const float*)d_in[8];
    const float* ln1b = (const float*)d_in[9];
    const float* ln2g = (const float*)d_in[10];
    const float* ln2b = (const float*)d_in[11];
    const float* W1   = (const float*)d_in[12];
    const float* b1   = (const float*)d_in[13];
    const float* W2   = (const float*)d_in[14];
    const float* b2   = (const float*)d_in[15];
    const float* lnfg = (const float*)d_in[16];
    const float* lnfb = (const float*)d_in[17];
    const float* Wh   = (const float*)d_in[18];
    const float* bh   = (const float*)d_in[19];
    float* out = (float*)d_out;

    float* x;
    __nv_bfloat16 *hhi,*hlo,*qhi,*qlo,*khi,*klo,*vhi,*vlo,*athi,*atlo,*ffhi,*fflo,*wbuf;
    cudaGetSymbolAddress((void**)&x, g_x);
    cudaGetSymbolAddress((void**)&hhi, g_hhi);  cudaGetSymbolAddress((void**)&hlo, g_hlo);
    cudaGetSymbolAddress((void**)&qhi, g_qhi);  cudaGetSymbolAddress((void**)&qlo, g_qlo);
    cudaGetSymbolAddress((void**)&khi, g_khi);  cudaGetSymbolAddress((void**)&klo, g_klo);
    cudaGetSymbolAddress((void**)&vhi, g_vhi);  cudaGetSymbolAddress((void**)&vlo, g_vlo);
    cudaGetSymbolAddress((void**)&athi, g_atthi); cudaGetSymbolAddress((void**)&atlo, g_attlo);
    cudaGetSymbolAddress((void**)&ffhi, g_ffhi); cudaGetSymbolAddress((void**)&fflo, g_fflo);
    cudaGetSymbolAddress((void**)&wbuf, g_wbuf);

    cudaFuncSetAttribute(attn_tc_kernel, cudaFuncAttributeMaxDynamicSharedMemorySize, ATT_SMEM);
    cudaFuncSetAttribute(gemm_tc_kernel<false,false,false,true>, cudaFuncAttributeMaxDynamicSharedMemorySize, GEMM_SMEM);
    cudaFuncSetAttribute(gemm_tc_kernel<true,true,false,true>,   cudaFuncAttributeMaxDynamicSharedMemorySize, GEMM_SMEM);
    cudaFuncSetAttribute(gemm_tc_kernel<true,false,true,false>,  cudaFuncAttributeMaxDynamicSharedMemorySize, GEMM_SMEM);
    cudaFuncSetAttribute(gemm_tc_kernel<true,false,false,false>, cudaFuncAttributeMaxDynamicSharedMemorySize, GEMM_SMEM);

    // ---- weight conversion ----
    const size_t M1 = 1048576, M4 = 4194304;
    const size_t layer_elems = 2 * (4 * M1 + 2 * M4);
    __nv_bfloat16* wh_hi = wbuf + 6 * layer_elems;
    __nv_bfloat16* wh_lo = wh_hi + (size_t)VOCAB * DMODEL;

    dim3 cblk(32, 8);
    for (int l = 0; l < NLAYER; l++) {
        __nv_bfloat16* base = wbuf + l * layer_elems;
        __nv_bfloat16* wq_hi = base;            __nv_bfloat16* wq_lo = base + M1;
        __nv_bfloat16* wk_hi = base + 2*M1;     __nv_bfloat16* wk_lo = base + 3*M1;
        __nv_bfloat16* wv_hi = base + 4*M1;     __nv_bfloat16* wv_lo = base + 5*M1;
        __nv_bfloat16* wo_hi = base + 6*M1;     __nv_bfloat16* wo_lo = base + 7*M1;
        __nv_bfloat16* w1_hi = base + 8*M1;     __nv_bfloat16* w1_lo = w1_hi + M4;
        __nv_bfloat16* w2_hi = w1_hi + 2*M4;    __nv_bfloat16* w2_lo = w2_hi + M4;

        convw_kernel<true><<<dim3(32,32), cblk>>>(Wq + l*M1, wq_hi, wq_lo, DMODEL, DMODEL);
        convw_kernel<true><<<dim3(32,32), cblk>>>(Wk + l*M1, wk_hi, wk_lo, DMODEL, DMODEL);
        convw_kernel<true><<<dim3(32,32), cblk>>>(Wv + l*M1, wv_hi, wv_lo, DMODEL, DMODEL);
        convw_kernel<false><<<dim3(32,32), cblk>>>(Wo + l*M1, wo_hi, wo_lo, DMODEL, DMODEL);
        convw_kernel<false><<<dim3(128,32), cblk>>>(W1 + l*M4, w1_hi, w1_lo, DMODEL, DFF);
        convw_kernel<false><<<dim3(32,128), cblk>>>(W2 + l*M4, w2_hi, w2_lo, DFF, DMODEL);
    }
    convw_kernel<false><<<dim3(VOCAB/32, 32), cblk>>>(Wh, wh_hi, wh_lo, DMODEL, VOCAB);

    // ---- forward ----
    embed_kernel<<<NROWS, 256>>>(idx, tok, pos, x);

    dim3 gD(DMODEL/BN, NROWS/BM);
    dim3 gF(DFF/BN, NROWS/BM);
    dim3 gV(VOCAB/BN, NROWS/BM);

    for (int l = 0; l < NLAYER; l++) {
        __nv_bfloat16* base = wbuf + l * layer_elems;
        __nv_bfloat16* wq_hi = base;            __nv_bfloat16* wq_lo = base + M1;
        __nv_bfloat16* wk_hi = base + 2*M1;     __nv_bfloat16* wk_lo = base + 3*M1;
        __nv_bfloat16* wv_hi = base + 4*M1;     __nv_bfloat16* wv_lo = base + 5*M1;
        __nv_bfloat16* wo_hi = base + 6*M1;     __nv_bfloat16* wo_lo = base + 7*M1;
        __nv_bfloat16* w1_hi = base + 8*M1;     __nv_bfloat16* w1_lo = w1_hi + M4;
        __nv_bfloat16* w2_hi = w1_hi + 2*M4;    __nv_bfloat16* w2_lo = w2_hi + M4;

        ln_split_kernel<<<NROWS, 256>>>(x, ln1g + l*DMODEL, ln1b + l*DMODEL, hhi, hlo);
        gemm_tc_kernel<false,false,false,true><<<gD, 256, GEMM_SMEM>>>(
            hhi, hlo, wq_hi, wq_lo, nullptr, nullptr, nullptr, qhi, qlo, DMODEL, DMODEL);
        gemm_tc_kernel<false,false,false,true><<<gD, 256, GEMM_SMEM>>>(
            hhi, hlo, wk_hi, wk_lo, nullptr, nullptr, nullptr, khi, klo, DMODEL, DMODEL);
        gemm_tc_kernel<false,false,false,true><<<gD, 256, GEMM_SMEM>>>(
            hhi, hlo, wv_hi, wv_lo, nullptr, nullptr, nullptr, vhi, vlo, DMODEL, DMODEL);

        attn_tc_kernel<<<dim3(TLEN/64, NHEAD, BATCH), 128, ATT_SMEM>>>(
            qhi, qlo, khi, klo, vhi, vlo, athi, atlo);

        gemm_tc_kernel<true,false,true,false><<<gD, 256, GEMM_SMEM>>>(
            athi, atlo, wo_hi, wo_lo, bo + l*DMODEL, x, x, nullptr, nullptr, DMODEL, DMODEL);

        ln_split_kernel<<<NROWS, 256>>>(x, ln2g + l*DMODEL, ln2b + l*DMODEL, hhi, hlo);
        gemm_tc_kernel<true,true,false,true><<<gF, 256, GEMM_SMEM>>>(
            hhi, hlo, w1_hi, w1_lo, b1 + (size_t)l*DFF, nullptr, nullptr, ffhi, fflo, DFF, DMODEL);

        gemm_tc_kernel<true,false,true,false><<<gD, 256, GEMM_SMEM>>>(
            ffhi, fflo, w2_hi, w2_lo, b2 + l*DMODEL, x, x, nullptr, nullptr, DMODEL, DFF);
    }

    ln_split_kernel<<<NROWS, 256>>>(x, lnfg, lnfb, hhi, hlo);
    gemm_tc_kernel<true,false,false,false><<<gV, 256, GEMM_SMEM>>>(
        hhi, hlo, wh_hi, wh_lo, bh, nullptr, out, nullptr, nullptr, VOCAB, DMODEL);
}